// round 14
// baseline (speedup 1.0000x reference)
#include <cuda_runtime.h>

// Problem constants (fixed by setup_inputs)
#define BB  2
#define CC  32
#define TT  64
#define HH  64
#define WW  64
#define HWSZ 4096          // H*W
#define NN  512
#define CF  32
#define CHN 16
#define FT  400            // featT == orgt == 400
#define LL  (FT*NN)        // 204800
#define BL  (BB*LL)        // 409600
#define T_SCALE (63.0f/399.0f)
#define EPS 1e-5f

#define NBLK_HXG 256       // (b,t,nc) blocks in k_main
#define NBLK_R   512       // float4 r blocks in k_main
#define NBLK_ST  128       // (b,o,nc,th) blocks in k_stats2
#define NBLK_OUT 512       // (b,s,nc,half): 2*64*2*2 blocks in k_final
#define NBLK_RES 3200      // float4 result blocks in k_final

// Scratch (static device allocations; no cudaMalloc allowed)
__device__ float g_hx[BB*CHN*TT*NN];    // W1f@gather(x) at source T: [b][o][t][n]  4 MB
__device__ float g_r [BB*TT*HWSZ];      // Wr@x head: [b][t][hw]   2 MB
__device__ float g_part[NBLK_ST*2];     // per-block (sum, sumsq)
// per-source-row stat coefficient tables + t-range per bucket
__device__ float g_rowA[64], g_rowQ[64], g_cross[64];
__device__ int   g_tstart[65];

// ---------------------------------------------------------------------------
// K_MAIN: fused independent work, no prep kernel.
//   blocks [0, 256):    hxg — computes W1f/b1f IN-BLOCK, then
//                       hx[b][o][t][n] = W1f @ x[b][:,t,coord_n] + b1f
//   blocks [256, 768):  r — r[b][t][hw] = Wr @ x (float4 stream)
//   block  768:         weight-table scan (runs hidden behind the x stream)
__global__ void __launch_bounds__(256, 4)
k_main(const float* __restrict__ x, const int* __restrict__ coord,
       const float* __restrict__ Wr, const float* __restrict__ br,
       const float* __restrict__ W1, const float* __restrict__ b1,
       const float* __restrict__ Wf, const float* __restrict__ bf) {
    int tid = threadIdx.x;
    if (blockIdx.x < NBLK_HXG) {
        __shared__ float sW[CHN*CF];
        __shared__ float sb[CHN];
        // In-block fold: W1f = W1@Wf (512 entries, 2 per thread), b1f = W1@bf+b1
#pragma unroll
        for (int rep = 0; rep < 2; ++rep) {
            int i = tid + rep*256;
            int o = i >> 5, c = i & 31;
            float acc = 0.f;
#pragma unroll
            for (int k = 0; k < CF; ++k) acc += __ldg(W1 + o*CF + k) * __ldg(Wf + k*CC + c);
            sW[i] = acc;
        }
        if (tid < CHN) {
            float a = __ldg(b1 + tid);
#pragma unroll
            for (int k = 0; k < CF; ++k) a += __ldg(W1 + tid*CF + k) * __ldg(bf + k);
            sb[tid] = a;
        }
        int blk = blockIdx.x;
        int nc = blk & 1;
        int bt = blk >> 1;
        int b = bt >> 6, t = bt & 63;
        __syncthreads();

        int n = nc*256 + tid;
        int ch = __ldg(coord + ((size_t)(b*NN + n))*2);
        int cw = __ldg(coord + ((size_t)(b*NN + n))*2 + 1);
        const float* xp = x + ((size_t)(b*CC)*TT + t)*HWSZ + ch*WW + cw;

        float hv[CHN];
#pragma unroll
        for (int o = 0; o < CHN; ++o) hv[o] = sb[o];
#pragma unroll
        for (int c = 0; c < CC; ++c) {
            float v = __ldg(xp + (size_t)c*TT*HWSZ);
#pragma unroll
            for (int o = 0; o < CHN; ++o) hv[o] += sW[o*CF + c] * v;
        }
        float* hp = g_hx + (((size_t)b*CHN)*TT + t)*NN + n;
#pragma unroll
        for (int o = 0; o < CHN; ++o) hp[(size_t)o*TT*NN] = hv[o];
    } else if (blockIdx.x < NBLK_HXG + NBLK_R) {
        int gid = (blockIdx.x - NBLK_HXG) * 256 + tid;   // < B*T*HW/4 = 131072
        int hw4 = gid & (HWSZ/4 - 1);
        int bt  = gid >> 10;                             // b*T + t
        int b   = bt >> 6, t = bt & 63;
        const float4* xp = (const float4*)(x + ((size_t)b*CC*TT + t)*HWSZ) + hw4;
        float brv = __ldg(br);
        float4 acc = make_float4(brv, brv, brv, brv);
#pragma unroll
        for (int c = 0; c < CC; ++c) {
            float wv = __ldg(Wr + c);
            float4 v = __ldg(xp + (size_t)c*TT*HWSZ/4);
            acc.x += wv*v.x; acc.y += wv*v.y; acc.z += wv*v.z; acc.w += wv*v.w;
        }
        ((float4*)g_r)[gid] = acc;
    } else {
        // Weight-table scan block: per-bucket scan with the EXACT float formula.
        __shared__ float sSa[64], sSb[64], sQa[64], sQab[64], sQb[64];
        if (tid < 64) {
            int s = tid;
            float Sa = 0.f, Sb = 0.f, Qa = 0.f, Qab = 0.f, Qb = 0.f;
            int tstart = FT;
            for (int tt = 0; tt < FT; ++tt) {
                float pos = (float)tt * T_SCALE;
                int i0 = (int)floorf(pos);
                if (i0 > 63) i0 = 63;
                float w = pos - (float)i0;
                if (i0 >= s && tstart == FT) tstart = tt;
                if (i0 == s) {
                    float u = 1.f - w;
                    Sa += u;  Sb += w;
                    Qa += u*u; Qab += u*w; Qb += w*w;
                }
            }
            sSa[s] = Sa; sSb[s] = Sb; sQa[s] = Qa; sQab[s] = Qab; sQb[s] = Qb;
            g_tstart[s] = tstart;
            if (s == 63) g_tstart[64] = FT;
        }
        __syncthreads();
        if (tid < 64) {
            int t = tid;
            float rA = sSa[t] + (t > 0 ? sSb[t-1] : 0.f) + (t == 63 ? sSb[63] : 0.f);
            float rQ = sQa[t] + (t > 0 ? sQb[t-1] : 0.f)
                     + (t == 63 ? (sQb[63] + 2.f*sQab[63]) : 0.f);
            g_rowA[t]  = rA;
            g_rowQ[t]  = rQ;
            g_cross[t] = (t < 63) ? 2.f*sQab[t] : 0.f;
        }
    }
}

// ---------------------------------------------------------------------------
// K_STATS2: per-(b,o,nc,th) block; thread walks its half of the t-range,
// accumulating row-weighted sum and sumsq (incl. cross term) in registers.
// grid = 128, block = 256
__global__ void __launch_bounds__(256)
k_stats2() {
    __shared__ float sA[64], sQ[64], sX[64];
    __shared__ float red[8][2];
    int tid = threadIdx.x;
    if (tid < 64)               sA[tid]      = g_rowA[tid];
    else if (tid < 128)         sQ[tid-64]   = g_rowQ[tid-64];
    else if (tid < 192)         sX[tid-128]  = g_cross[tid-128];
    int blk = blockIdx.x;                    // (((b*16+o)*2+nc)*2+th)
    int th = blk & 1;
    int nc = (blk >> 1) & 1;
    int o  = (blk >> 2) & 15;
    int b  = blk >> 6;
    int n  = nc*256 + tid;
    int lo = th * 32;
    __syncthreads();

    const float* hp = g_hx + (((size_t)b*CHN + o)*TT)*NN + n;
    float v = 0.f, q = 0.f;
    float cur = hp[(size_t)lo*NN];
#pragma unroll 8
    for (int i = 0; i < 32; ++i) {
        int t = lo + i;
        float nxt = (t + 1 < TT) ? hp[(size_t)(t+1)*NN] : 0.f;
        v += sA[t]*cur;
        q += sQ[t]*cur*cur + sX[t]*cur*nxt;
        cur = nxt;
    }

    int warp = tid >> 5, lane = tid & 31;
#pragma unroll
    for (int off = 16; off; off >>= 1) {
        v += __shfl_down_sync(0xffffffffu, v, off);
        q += __shfl_down_sync(0xffffffffu, q, off);
    }
    if (lane == 0) { red[warp][0] = v; red[warp][1] = q; }
    __syncthreads();
    if (tid < 2) {
        float a = 0.f;
#pragma unroll
        for (int wp = 0; wp < 8; ++wp) a += red[wp][tid];
        g_part[blk*2 + tid] = a;
    }
}

// ---------------------------------------------------------------------------
// K_FINAL: fused output kernels.
//   blocks [0, 512):   out — two-phase: (1) v = relu(BN(lerp(hx))) -> smem,
//                      (2) 2-row W2 tile in registers, each LDS.128 feeds 2
//                      output rows (halves smem crossbar traffic).
//   blocks [512, 3712): result — lerp_t(r) (float4)
__global__ void __launch_bounds__(256)
k_final(const float* __restrict__ gamma, const float* __restrict__ beta,
        const float* __restrict__ W2, const float* __restrict__ b2,
        float* __restrict__ out, float* __restrict__ outR) {
    int tid = threadIdx.x;
    if (blockIdx.x < NBLK_OUT) {
        __shared__ float vbuf[CHN][256];       // 16KB activation tile
        __shared__ float sScale[CHN];
        __shared__ float sShift[CHN];
        if (tid < CHN) {
            int o = tid;
            // Deterministic fixed-order reduction of the 8 (b,nc,th) partials.
            float sv = 0.f, sq = 0.f;
#pragma unroll
            for (int b = 0; b < BB; ++b)
#pragma unroll
                for (int nc = 0; nc < 2; ++nc)
#pragma unroll
                    for (int th = 0; th < 2; ++th) {
                        int pb = (((b*16 + o)*2 + nc)*2 + th);
                        sv += g_part[pb*2];
                        sq += g_part[pb*2 + 1];
                    }
            float mu  = sv / (float)BL;
            float var = sq / (float)BL - mu*mu;
            float inv = rsqrtf(var + EPS);
            float sc  = gamma[o] * inv;
            sScale[o] = sc;
            sShift[o] = beta[o] - mu*sc;
        }
        __syncthreads();

        int blk  = blockIdx.x;                 // 0..511
        int half = blk & 1;
        int nc   = (blk >> 1) & 1;
        int bs   = blk >> 2;                   // 0..127
        int b = bs >> 6, s = bs & 63;          // b in 0..1
        int t0 = g_tstart[s], t1 = g_tstart[s+1];
        if (t0 + half >= t1) return;
        int s1 = min(s + 1, TT - 1);

        // phase-1 state: this thread's n column
        int n = nc*256 + tid;
        const float* pa = g_hx + ((size_t)b*CHN)*TT*NN + (size_t)s *NN + n;
        const float* pb = g_hx + ((size_t)b*CHN)*TT*NN + (size_t)s1*NN + n;
        float av[CHN], dv[CHN];
#pragma unroll
        for (int o = 0; o < CHN; ++o) {
            av[o] = pa[(size_t)o*TT*NN];
            dv[o] = pb[(size_t)o*TT*NN] - av[o];
        }

        // phase-2 state: 2 W2 rows per thread (o2 = 2g, 2g+1), quads m and m+32
        int g = tid >> 5;           // 0..7
        int m = tid & 31;           // 0..31
        float w2a[CHN], w2b[CHN];
#pragma unroll
        for (int o = 0; o < CHN; ++o) {
            w2a[o] = __ldg(W2 + (2*g  )*CHN + o);
            w2b[o] = __ldg(W2 + (2*g+1)*CHN + o);
        }
        float biasA = __ldg(b2 + 2*g);
        float biasB = __ldg(b2 + 2*g + 1);

        const float4* vb4 = (const float4*)&vbuf[0][0];   // [CHN][64] float4 view
        float* rowA = out + (size_t)b*CHN*LL + (size_t)(2*g  )*LL + nc*256;
        float* rowB = out + (size_t)b*CHN*LL + (size_t)(2*g+1)*LL + nc*256;

        for (int t = t0 + half; t < t1; t += 2) {
            float pos = (float)t * T_SCALE;
            float w = pos - floorf(pos);
            // phase 1: compute v for my n, publish to smem
#pragma unroll
            for (int o = 0; o < CHN; ++o) {
                float h = av[o] + dv[o] * w;
                vbuf[o][tid] = fmaxf(h * sScale[o] + sShift[o], 0.f);
            }
            __syncthreads();
            // phase 2: 2x2 tile (o2 in {2g,2g+1}) x (quads m, m+32)
            float4 a0 = make_float4(biasA, biasA, biasA, biasA);
            float4 a1 = a0;
            float4 c0 = make_float4(biasB, biasB, biasB, biasB);
            float4 c1 = c0;
#pragma unroll
            for (int o = 0; o < CHN; ++o) {
                float4 v0 = vb4[o*64 + m];
                float4 v1 = vb4[o*64 + m + 32];
                float wa = w2a[o], wb = w2b[o];
                a0.x += wa*v0.x; a0.y += wa*v0.y; a0.z += wa*v0.z; a0.w += wa*v0.w;
                a1.x += wa*v1.x; a1.y += wa*v1.y; a1.z += wa*v1.z; a1.w += wa*v1.w;
                c0.x += wb*v0.x; c0.y += wb*v0.y; c0.z += wb*v0.z; c0.w += wb*v0.w;
                c1.x += wb*v1.x; c1.y += wb*v1.y; c1.z += wb*v1.z; c1.w += wb*v1.w;
            }
            float4* opA = (float4*)(rowA + (size_t)t*NN);
            float4* opB = (float4*)(rowB + (size_t)t*NN);
            opA[m]      = a0;
            opA[m + 32] = a1;
            opB[m]      = c0;
            opB[m + 32] = c1;
            __syncthreads();
        }
    } else {
        int gid = (blockIdx.x - NBLK_OUT) * 256 + tid;   // < B*FT*HW/4 = 819200
        int hw4 = gid & (HWSZ/4 - 1);
        int bt  = gid >> 10;                             // b*FT + t
        int b = bt / FT, t = bt - b*FT;
        float pos = (float)t * T_SCALE;
        int i0 = (int)floorf(pos);
        float w = pos - (float)i0;
        int i1 = min(i0 + 1, TT - 1);
        float4 a = ((const float4*)g_r)[((size_t)b*TT + i0)*(HWSZ/4) + hw4];
        float4 c = ((const float4*)g_r)[((size_t)b*TT + i1)*(HWSZ/4) + hw4];
        float4 o;
        o.x = a.x + (c.x - a.x)*w;
        o.y = a.y + (c.y - a.y)*w;
        o.z = a.z + (c.z - a.z)*w;
        o.w = a.w + (c.w - a.w)*w;
        ((float4*)outR)[gid] = o;
    }
}

// ---------------------------------------------------------------------------
extern "C" void kernel_launch(void* const* d_in, const int* in_sizes, int n_in,
                              void* d_out, int out_size) {
    const float* x     = (const float*)d_in[0];
    const int*   coord = (const int*)  d_in[1];
    const float* Wf    = (const float*)d_in[2];
    const float* bf    = (const float*)d_in[3];
    const float* Wr    = (const float*)d_in[4];
    const float* br    = (const float*)d_in[5];
    const float* W1    = (const float*)d_in[6];
    const float* b1    = (const float*)d_in[7];
    const float* gamma = (const float*)d_in[8];
    const float* beta  = (const float*)d_in[9];
    const float* W2    = (const float*)d_in[10];
    const float* b2    = (const float*)d_in[11];

    float* out  = (float*)d_out;                 // [B,CH,L]   = 6,553,600 floats
    float* outR = out + (size_t)BB*CHN*LL;       // [B,1,FT,H,W] = 3,276,800 floats

    k_main<<<NBLK_HXG + NBLK_R + 1, 256>>>(x, coord, Wr, br, W1, b1, Wf, bf);
    k_stats2<<<NBLK_ST, 256>>>();
    k_final<<<NBLK_OUT + NBLK_RES, 256>>>(gamma, beta, W2, b2, out, outR);
}

// round 15
// speedup vs baseline: 1.1000x; 1.1000x over previous
#include <cuda_runtime.h>

// Problem constants (fixed by setup_inputs)
#define BB  2
#define CC  32
#define TT  64
#define HH  64
#define WW  64
#define HWSZ 4096          // H*W
#define NN  512
#define CF  32
#define CHN 16
#define FT  400            // featT == orgt == 400
#define LL  (FT*NN)        // 204800
#define BL  (BB*LL)        // 409600
#define T_SCALE (63.0f/399.0f)
#define EPS 1e-5f

#define NBLK_HXG 256       // (b,t,nc) blocks in k_main
#define NBLK_R   512       // float4 r blocks in k_main
#define NBLK_ST  128       // (b,o,nc,th) stats blocks in k_mid
#define NBLK_RES 3200      // float4 result blocks in k_mid
#define NBLK_OUT 512       // (b,s,nc,half): 2*64*2*2 blocks in k_out

// Scratch (static device allocations; no cudaMalloc allowed)
__device__ float g_hx[BB*CHN*TT*NN];    // W1f@gather(x) at source T: [b][o][t][n]  4 MB
__device__ float g_r [BB*TT*HWSZ];      // Wr@x head: [b][t][hw]   2 MB
__device__ float g_part[NBLK_ST*2];     // per-block (sum, sumsq)
// per-source-row stat coefficient tables + t-range per bucket
__device__ float g_rowA[64], g_rowQ[64], g_cross[64];
__device__ int   g_tstart[65];

// ---------------------------------------------------------------------------
// K_MAIN: fused independent work, no prep kernel.
//   blocks [0, 256):    hxg — computes W1f/b1f IN-BLOCK, then
//                       hx[b][o][t][n] = W1f @ x[b][:,t,coord_n] + b1f
//   blocks [256, 768):  r — r[b][t][hw] = Wr @ x (float4 stream)
//   block  768:         weight-table scan (runs hidden behind the x stream)
__global__ void __launch_bounds__(256, 3)
k_main(const float* __restrict__ x, const int* __restrict__ coord,
       const float* __restrict__ Wr, const float* __restrict__ br,
       const float* __restrict__ W1, const float* __restrict__ b1,
       const float* __restrict__ Wf, const float* __restrict__ bf) {
    int tid = threadIdx.x;
    if (blockIdx.x < NBLK_HXG) {
        __shared__ float sW[CHN*CF];
        __shared__ float sb[CHN];
        // In-block fold: W1f = W1@Wf (512 entries, 2 per thread), b1f = W1@bf+b1
#pragma unroll
        for (int rep = 0; rep < 2; ++rep) {
            int i = tid + rep*256;
            int o = i >> 5, c = i & 31;
            float acc = 0.f;
#pragma unroll
            for (int k = 0; k < CF; ++k) acc += __ldg(W1 + o*CF + k) * __ldg(Wf + k*CC + c);
            sW[i] = acc;
        }
        if (tid < CHN) {
            float a = __ldg(b1 + tid);
#pragma unroll
            for (int k = 0; k < CF; ++k) a += __ldg(W1 + tid*CF + k) * __ldg(bf + k);
            sb[tid] = a;
        }
        int blk = blockIdx.x;
        int nc = blk & 1;
        int bt = blk >> 1;
        int b = bt >> 6, t = bt & 63;
        __syncthreads();

        int n = nc*256 + tid;
        int ch = __ldg(coord + ((size_t)(b*NN + n))*2);
        int cw = __ldg(coord + ((size_t)(b*NN + n))*2 + 1);
        const float* xp = x + ((size_t)(b*CC)*TT + t)*HWSZ + ch*WW + cw;

        float hv[CHN];
#pragma unroll
        for (int o = 0; o < CHN; ++o) hv[o] = sb[o];
#pragma unroll
        for (int c = 0; c < CC; ++c) {
            float v = __ldg(xp + (size_t)c*TT*HWSZ);
#pragma unroll
            for (int o = 0; o < CHN; ++o) hv[o] += sW[o*CF + c] * v;
        }
        float* hp = g_hx + (((size_t)b*CHN)*TT + t)*NN + n;
#pragma unroll
        for (int o = 0; o < CHN; ++o) hp[(size_t)o*TT*NN] = hv[o];
    } else if (blockIdx.x < NBLK_HXG + NBLK_R) {
        int gid = (blockIdx.x - NBLK_HXG) * 256 + tid;   // < B*T*HW/4 = 131072
        int hw4 = gid & (HWSZ/4 - 1);
        int bt  = gid >> 10;                             // b*T + t
        int b   = bt >> 6, t = bt & 63;
        const float4* xp = (const float4*)(x + ((size_t)b*CC*TT + t)*HWSZ) + hw4;
        float brv = __ldg(br);
        float4 acc = make_float4(brv, brv, brv, brv);
#pragma unroll
        for (int c = 0; c < CC; ++c) {
            float wv = __ldg(Wr + c);
            float4 v = __ldg(xp + (size_t)c*TT*HWSZ/4);
            acc.x += wv*v.x; acc.y += wv*v.y; acc.z += wv*v.z; acc.w += wv*v.w;
        }
        ((float4*)g_r)[gid] = acc;
    } else {
        // Weight-table scan block: per-bucket scan with the EXACT float formula.
        __shared__ float sSa[64], sSb[64], sQa[64], sQab[64], sQb[64];
        if (tid < 64) {
            int s = tid;
            float Sa = 0.f, Sb = 0.f, Qa = 0.f, Qab = 0.f, Qb = 0.f;
            int tstart = FT;
            for (int tt = 0; tt < FT; ++tt) {
                float pos = (float)tt * T_SCALE;
                int i0 = (int)floorf(pos);
                if (i0 > 63) i0 = 63;
                float w = pos - (float)i0;
                if (i0 >= s && tstart == FT) tstart = tt;
                if (i0 == s) {
                    float u = 1.f - w;
                    Sa += u;  Sb += w;
                    Qa += u*u; Qab += u*w; Qb += w*w;
                }
            }
            sSa[s] = Sa; sSb[s] = Sb; sQa[s] = Qa; sQab[s] = Qab; sQb[s] = Qb;
            g_tstart[s] = tstart;
            if (s == 63) g_tstart[64] = FT;
        }
        __syncthreads();
        if (tid < 64) {
            int t = tid;
            float rA = sSa[t] + (t > 0 ? sSb[t-1] : 0.f) + (t == 63 ? sSb[63] : 0.f);
            float rQ = sQa[t] + (t > 0 ? sQb[t-1] : 0.f)
                     + (t == 63 ? (sQb[63] + 2.f*sQab[63]) : 0.f);
            g_rowA[t]  = rA;
            g_rowQ[t]  = rQ;
            g_cross[t] = (t < 63) ? 2.f*sQab[t] : 0.f;
        }
    }
}

// ---------------------------------------------------------------------------
// K_MID: fused stats + result-lerp (both depend only on k_main outputs).
//   blocks [0, 128):     stats — per-(b,o,nc,th), row-weighted sum/sumsq
//   blocks [128, 3328):  result — lerp_t(r) (float4 stream)
__global__ void __launch_bounds__(256)
k_mid(float* __restrict__ outR) {
    int tid = threadIdx.x;
    if (blockIdx.x < NBLK_ST) {
        __shared__ float sA[64], sQ[64], sX[64];
        __shared__ float red[8][2];
        if (tid < 64)               sA[tid]      = g_rowA[tid];
        else if (tid < 128)         sQ[tid-64]   = g_rowQ[tid-64];
        else if (tid < 192)         sX[tid-128]  = g_cross[tid-128];
        int blk = blockIdx.x;                    // (((b*16+o)*2+nc)*2+th)
        int th = blk & 1;
        int nc = (blk >> 1) & 1;
        int o  = (blk >> 2) & 15;
        int b  = blk >> 6;
        int n  = nc*256 + tid;
        int lo = th * 32;
        __syncthreads();

        const float* hp = g_hx + (((size_t)b*CHN + o)*TT)*NN + n;
        float v = 0.f, q = 0.f;
        float cur = hp[(size_t)lo*NN];
#pragma unroll 8
        for (int i = 0; i < 32; ++i) {
            int t = lo + i;
            float nxt = (t + 1 < TT) ? hp[(size_t)(t+1)*NN] : 0.f;
            v += sA[t]*cur;
            q += sQ[t]*cur*cur + sX[t]*cur*nxt;
            cur = nxt;
        }

        int warp = tid >> 5, lane = tid & 31;
#pragma unroll
        for (int off = 16; off; off >>= 1) {
            v += __shfl_down_sync(0xffffffffu, v, off);
            q += __shfl_down_sync(0xffffffffu, q, off);
        }
        if (lane == 0) { red[warp][0] = v; red[warp][1] = q; }
        __syncthreads();
        if (tid < 2) {
            float a = 0.f;
#pragma unroll
            for (int wp = 0; wp < 8; ++wp) a += red[wp][tid];
            g_part[blk*2 + tid] = a;
        }
    } else {
        int gid = (blockIdx.x - NBLK_ST) * 256 + tid;    // < B*FT*HW/4 = 819200
        int hw4 = gid & (HWSZ/4 - 1);
        int bt  = gid >> 10;                             // b*FT + t
        int b = bt / FT, t = bt - b*FT;
        float pos = (float)t * T_SCALE;
        int i0 = (int)floorf(pos);
        float w = pos - (float)i0;
        int i1 = min(i0 + 1, TT - 1);
        float4 a = ((const float4*)g_r)[((size_t)b*TT + i0)*(HWSZ/4) + hw4];
        float4 c = ((const float4*)g_r)[((size_t)b*TT + i1)*(HWSZ/4) + hw4];
        float4 o;
        o.x = a.x + (c.x - a.x)*w;
        o.y = a.y + (c.y - a.y)*w;
        o.z = a.z + (c.z - a.z)*w;
        o.w = a.w + (c.w - a.w)*w;
        ((float4*)outR)[gid] = o;
    }
}

// ---------------------------------------------------------------------------
// K_OUT: out = W2 @ relu(BN(lerp_t(hx))) + b2, two-phase smem scheme.
//   phase 1: v = relu(BN(lerp(hx))) -> smem
//   phase 2: 2-row W2 tile in registers; each LDS.128 feeds 2 output rows.
// grid = 512 (b, s, nc, t-parity), block = 256
__global__ void __launch_bounds__(256)
k_out(const float* __restrict__ gamma, const float* __restrict__ beta,
      const float* __restrict__ W2, const float* __restrict__ b2,
      float* __restrict__ out) {
    int tid = threadIdx.x;
    __shared__ float vbuf[CHN][256];       // 16KB activation tile
    __shared__ float sScale[CHN];
    __shared__ float sShift[CHN];
    if (tid < CHN) {
        int o = tid;
        // Deterministic fixed-order reduction of the 8 (b,nc,th) partials.
        float sv = 0.f, sq = 0.f;
#pragma unroll
        for (int b = 0; b < BB; ++b)
#pragma unroll
            for (int nc = 0; nc < 2; ++nc)
#pragma unroll
                for (int th = 0; th < 2; ++th) {
                    int pb = (((b*16 + o)*2 + nc)*2 + th);
                    sv += g_part[pb*2];
                    sq += g_part[pb*2 + 1];
                }
        float mu  = sv / (float)BL;
        float var = sq / (float)BL - mu*mu;
        float inv = rsqrtf(var + EPS);
        float sc  = gamma[o] * inv;
        sScale[o] = sc;
        sShift[o] = beta[o] - mu*sc;
    }
    __syncthreads();

    int blk  = blockIdx.x;                 // 0..511
    int half = blk & 1;
    int nc   = (blk >> 1) & 1;
    int bs   = blk >> 2;                   // 0..127
    int b = bs >> 6, s = bs & 63;          // b in 0..1
    int t0 = g_tstart[s], t1 = g_tstart[s+1];
    if (t0 + half >= t1) return;
    int s1 = min(s + 1, TT - 1);

    // phase-1 state: this thread's n column
    int n = nc*256 + tid;
    const float* pa = g_hx + ((size_t)b*CHN)*TT*NN + (size_t)s *NN + n;
    const float* pb = g_hx + ((size_t)b*CHN)*TT*NN + (size_t)s1*NN + n;
    float av[CHN], dv[CHN];
#pragma unroll
    for (int o = 0; o < CHN; ++o) {
        av[o] = pa[(size_t)o*TT*NN];
        dv[o] = pb[(size_t)o*TT*NN] - av[o];
    }

    // phase-2 state: 2 W2 rows per thread (o2 = 2g, 2g+1), quads m and m+32
    int g = tid >> 5;           // 0..7
    int m = tid & 31;           // 0..31
    float w2a[CHN], w2b[CHN];
#pragma unroll
    for (int o = 0; o < CHN; ++o) {
        w2a[o] = __ldg(W2 + (2*g  )*CHN + o);
        w2b[o] = __ldg(W2 + (2*g+1)*CHN + o);
    }
    float biasA = __ldg(b2 + 2*g);
    float biasB = __ldg(b2 + 2*g + 1);

    const float4* vb4 = (const float4*)&vbuf[0][0];   // [CHN][64] float4 view
    float* rowA = out + (size_t)b*CHN*LL + (size_t)(2*g  )*LL + nc*256;
    float* rowB = out + (size_t)b*CHN*LL + (size_t)(2*g+1)*LL + nc*256;

    for (int t = t0 + half; t < t1; t += 2) {
        float pos = (float)t * T_SCALE;
        float w = pos - floorf(pos);
        // phase 1: compute v for my n, publish to smem
#pragma unroll
        for (int o = 0; o < CHN; ++o) {
            float h = av[o] + dv[o] * w;
            vbuf[o][tid] = fmaxf(h * sScale[o] + sShift[o], 0.f);
        }
        __syncthreads();
        // phase 2: 2x2 tile (o2 in {2g,2g+1}) x (quads m, m+32)
        float4 a0 = make_float4(biasA, biasA, biasA, biasA);
        float4 a1 = a0;
        float4 c0 = make_float4(biasB, biasB, biasB, biasB);
        float4 c1 = c0;
#pragma unroll
        for (int o = 0; o < CHN; ++o) {
            float4 v0 = vb4[o*64 + m];
            float4 v1 = vb4[o*64 + m + 32];
            float wa = w2a[o], wb = w2b[o];
            a0.x += wa*v0.x; a0.y += wa*v0.y; a0.z += wa*v0.z; a0.w += wa*v0.w;
            a1.x += wa*v1.x; a1.y += wa*v1.y; a1.z += wa*v1.z; a1.w += wa*v1.w;
            c0.x += wb*v0.x; c0.y += wb*v0.y; c0.z += wb*v0.z; c0.w += wb*v0.w;
            c1.x += wb*v1.x; c1.y += wb*v1.y; c1.z += wb*v1.z; c1.w += wb*v1.w;
        }
        float4* opA = (float4*)(rowA + (size_t)t*NN);
        float4* opB = (float4*)(rowB + (size_t)t*NN);
        opA[m]      = a0;
        opA[m + 32] = a1;
        opB[m]      = c0;
        opB[m + 32] = c1;
        __syncthreads();
    }
}

// ---------------------------------------------------------------------------
extern "C" void kernel_launch(void* const* d_in, const int* in_sizes, int n_in,
                              void* d_out, int out_size) {
    const float* x     = (const float*)d_in[0];
    const int*   coord = (const int*)  d_in[1];
    const float* Wf    = (const float*)d_in[2];
    const float* bf    = (const float*)d_in[3];
    const float* Wr    = (const float*)d_in[4];
    const float* br    = (const float*)d_in[5];
    const float* W1    = (const float*)d_in[6];
    const float* b1    = (const float*)d_in[7];
    const float* gamma = (const float*)d_in[8];
    const float* beta  = (const float*)d_in[9];
    const float* W2    = (const float*)d_in[10];
    const float* b2    = (const float*)d_in[11];

    float* out  = (float*)d_out;                 // [B,CH,L]   = 6,553,600 floats
    float* outR = out + (size_t)BB*CHN*LL;       // [B,1,FT,H,W] = 3,276,800 floats

    k_main<<<NBLK_HXG + NBLK_R + 1, 256>>>(x, coord, Wr, br, W1, b1, Wf, bf);
    k_mid<<<NBLK_ST + NBLK_RES, 256>>>(outR);
    k_out<<<NBLK_OUT, 256>>>(gamma, beta, W2, b2, out);
}